// round 1
// baseline (speedup 1.0000x reference)
#include <cuda_runtime.h>
#include <stdint.h>
#include <math.h>

#define DIM   128
#define MAXN  50000
#define MAXE  1600000
#define ND    (MAXN * DIM)

// ---------------- device scratch (no allocs allowed) ----------------
__device__ int   g_deg[MAXN + 1];
__device__ int   g_rowptr[MAXN + 1];
__device__ int   g_cursor[MAXN + 1];
__device__ int   g_csrc[MAXE];
__device__ float g_u[2 * ND];   // combined (1+eps)h + agg, per path
__device__ float g_h[2 * ND];   // layer outputs, per path
__device__ float g_g[2 * ND];   // final GEMM outputs, per path

// ---------------- CSR build ----------------
__global__ void zero_deg_kernel(int n) {
    int i = blockIdx.x * blockDim.x + threadIdx.x;
    if (i <= n) g_deg[i] = 0;
}

__global__ void hist_kernel(const int* __restrict__ dst, int e) {
    int i = blockIdx.x * blockDim.x + threadIdx.x;
    if (i < e) atomicAdd(&g_deg[dst[i]], 1);
}

__global__ void scan_kernel(int n) {
    __shared__ int sd[1024];
    int t = threadIdx.x;
    int items = (n + 1023) >> 10;
    int base = t * items;
    int s = 0;
    for (int i = 0; i < items; i++) {
        int idx = base + i;
        if (idx < n) s += g_deg[idx];
    }
    sd[t] = s;
    __syncthreads();
    for (int o = 1; o < 1024; o <<= 1) {
        int v = (t >= o) ? sd[t - o] : 0;
        __syncthreads();
        sd[t] += v;
        __syncthreads();
    }
    int run = (t == 0) ? 0 : sd[t - 1];
    for (int i = 0; i < items; i++) {
        int idx = base + i;
        if (idx < n) {
            g_rowptr[idx] = run;
            g_cursor[idx] = run;
            run += g_deg[idx];
            if (idx == n - 1) g_rowptr[n] = run;
        }
    }
}

__global__ void fill_kernel(const int* __restrict__ src, const int* __restrict__ dst, int e) {
    int i = blockIdx.x * blockDim.x + threadIdx.x;
    if (i < e) {
        int p = atomicAdd(&g_cursor[dst[i]], 1);
        g_csrc[p] = src[i];
    }
}

// ---------------- SpMM + combine: u = (1+eps)*h + sum_{j->i} h_j ----------------
// warp per dst row, lane owns 4 of the 128 features. Handles both paths.
__global__ void spmm_kernel(const float* __restrict__ hm, const float* __restrict__ hs,
                            const float* __restrict__ epsm, const float* __restrict__ epss,
                            int layer,
                            float* __restrict__ um, float* __restrict__ us,
                            int same, int n) {
    int gw = (blockIdx.x * blockDim.x + threadIdx.x) >> 5;
    int lane = threadIdx.x & 31;
    if (gw >= n) return;
    int rp0 = g_rowptr[gw], rp1 = g_rowptr[gw + 1];
    const float4* hm4 = (const float4*)hm;
    const float4* hs4 = (const float4*)hs;
    float4 am = make_float4(0.f, 0.f, 0.f, 0.f);
    float4 as = make_float4(0.f, 0.f, 0.f, 0.f);
    for (int j = rp0; j < rp1; ++j) {
        int s = __ldg(&g_csrc[j]);
        float4 v = __ldg(&hm4[s * 32 + lane]);
        am.x += v.x; am.y += v.y; am.z += v.z; am.w += v.w;
        if (!same) {
            float4 w = __ldg(&hs4[s * 32 + lane]);
            as.x += w.x; as.y += w.y; as.z += w.z; as.w += w.w;
        }
    }
    if (same) as = am;
    float cm = 1.0f + __ldg(&epsm[layer]);
    float cs = 1.0f + __ldg(&epss[layer]);
    float4 h0m = __ldg(&hm4[gw * 32 + lane]);
    float4 h0s = same ? h0m : __ldg(&hs4[gw * 32 + lane]);
    float4 om, os;
    om.x = fmaf(cm, h0m.x, am.x); om.y = fmaf(cm, h0m.y, am.y);
    om.z = fmaf(cm, h0m.z, am.z); om.w = fmaf(cm, h0m.w, am.w);
    os.x = fmaf(cs, h0s.x, as.x); os.y = fmaf(cs, h0s.y, as.y);
    os.z = fmaf(cs, h0s.z, as.z); os.w = fmaf(cs, h0s.w, as.w);
    ((float4*)um)[gw * 32 + lane] = om;
    ((float4*)us)[gw * 32 + lane] = os;
}

// ---------------- GEMM tile helpers ----------------
// 128-row x 128-col output tile, 256 threads (16x16), each thread 8x8.
// rows strided by 16 (broadcast-friendly smem reads), cols = tc*8..tc*8+7.
__device__ __forceinline__ void gemm_tile(const float* __restrict__ sW,
                                          const float* __restrict__ sA,
                                          int tr, int tc, float acc[8][8]) {
#pragma unroll 4
    for (int k = 0; k < DIM; k++) {
        float4 w0 = ((const float4*)sW)[k * 32 + tc * 2];
        float4 w1 = ((const float4*)sW)[k * 32 + tc * 2 + 1];
        float a[8];
#pragma unroll
        for (int i = 0; i < 8; i++) a[i] = sA[(tr + 16 * i) * DIM + k];
#pragma unroll
        for (int i = 0; i < 8; i++) {
            acc[i][0] = fmaf(a[i], w0.x, acc[i][0]);
            acc[i][1] = fmaf(a[i], w0.y, acc[i][1]);
            acc[i][2] = fmaf(a[i], w0.z, acc[i][2]);
            acc[i][3] = fmaf(a[i], w0.w, acc[i][3]);
            acc[i][4] = fmaf(a[i], w1.x, acc[i][4]);
            acc[i][5] = fmaf(a[i], w1.y, acc[i][5]);
            acc[i][6] = fmaf(a[i], w1.z, acc[i][6]);
            acc[i][7] = fmaf(a[i], w1.w, acc[i][7]);
        }
    }
}

__device__ __forceinline__ void load_weight(const float* __restrict__ W, float* sW, int t) {
    const float4* w4 = (const float4*)W;
    float4* d4 = (float4*)sW;
#pragma unroll
    for (int i = 0; i < 16; i++) d4[t + i * 256] = __ldg(&w4[t + i * 256]);
}

__device__ __forceinline__ void load_atile(const float* __restrict__ U, float* sA,
                                           int t, int row0, int n) {
    const float4* u4 = (const float4*)U;
    float4* a4 = (float4*)sA;
#pragma unroll
    for (int i = 0; i < 16; i++) {
        int q = t + i * 256;
        int r = q >> 5, kq = q & 31;
        float4 v = make_float4(0.f, 0.f, 0.f, 0.f);
        if (row0 + r < n) v = __ldg(&u4[(row0 + r) * 32 + kq]);
        a4[q] = v;
    }
}

__device__ __forceinline__ float sigmoidf_dev(float x) {
    return 1.0f / (1.0f + expf(-x));
}

struct PathGemm {
    const float* U; const float* W1; const float* b1;
    const float* W2; const float* b2; float* Hout;
};

// Fused MLP layer: Hout = sigmoid(U@W1 + b1) @ W2 + b2, grid.y selects path.
__global__ __launch_bounds__(256, 1) void mlp_kernel(PathGemm pa, PathGemm pb, int n) {
    extern __shared__ float smem[];
    float* sW = smem;
    float* sA = smem + DIM * DIM;
    PathGemm P = blockIdx.y ? pb : pa;
    int t = threadIdx.x;
    int tr = t >> 4, tc = t & 15;
    int row0 = blockIdx.x * 128;

    load_weight(P.W1, sW, t);
    load_atile(P.U, sA, t, row0, n);
    __syncthreads();

    float acc[8][8];
#pragma unroll
    for (int i = 0; i < 8; i++)
#pragma unroll
        for (int j = 0; j < 8; j++) acc[i][j] = 0.f;

    gemm_tile(sW, sA, tr, tc, acc);
    __syncthreads();   // all reads of sW/sA done

    float b1v[8];
#pragma unroll
    for (int j = 0; j < 8; j++) b1v[j] = __ldg(&P.b1[tc * 8 + j]);

#pragma unroll
    for (int i = 0; i < 8; i++) {
        int r = tr + 16 * i;
        float4 v0, v1;
        v0.x = sigmoidf_dev(acc[i][0] + b1v[0]);
        v0.y = sigmoidf_dev(acc[i][1] + b1v[1]);
        v0.z = sigmoidf_dev(acc[i][2] + b1v[2]);
        v0.w = sigmoidf_dev(acc[i][3] + b1v[3]);
        v1.x = sigmoidf_dev(acc[i][4] + b1v[4]);
        v1.y = sigmoidf_dev(acc[i][5] + b1v[5]);
        v1.z = sigmoidf_dev(acc[i][6] + b1v[6]);
        v1.w = sigmoidf_dev(acc[i][7] + b1v[7]);
        ((float4*)sA)[r * 32 + tc * 2] = v0;
        ((float4*)sA)[r * 32 + tc * 2 + 1] = v1;
    }
    load_weight(P.W2, sW, t);
    __syncthreads();

#pragma unroll
    for (int i = 0; i < 8; i++)
#pragma unroll
        for (int j = 0; j < 8; j++) acc[i][j] = 0.f;

    gemm_tile(sW, sA, tr, tc, acc);

    float b2v[8];
#pragma unroll
    for (int j = 0; j < 8; j++) b2v[j] = __ldg(&P.b2[tc * 8 + j]);

#pragma unroll
    for (int i = 0; i < 8; i++) {
        int r = row0 + tr + 16 * i;
        if (r < n) {
            float4 v0, v1;
            v0.x = acc[i][0] + b2v[0]; v0.y = acc[i][1] + b2v[1];
            v0.z = acc[i][2] + b2v[2]; v0.w = acc[i][3] + b2v[3];
            v1.x = acc[i][4] + b2v[4]; v1.y = acc[i][5] + b2v[5];
            v1.z = acc[i][6] + b2v[6]; v1.w = acc[i][7] + b2v[7];
            ((float4*)P.Hout)[r * 32 + tc * 2] = v0;
            ((float4*)P.Hout)[r * 32 + tc * 2 + 1] = v1;
        }
    }
}

struct FinalArgs { const float* Hin; const float* Wo; const float* bo; float* G; };

// Final projection: G = Hin @ Wout + bout
__global__ __launch_bounds__(256, 1) void final_kernel(FinalArgs fa, FinalArgs fb, int n) {
    extern __shared__ float smem[];
    float* sW = smem;
    float* sA = smem + DIM * DIM;
    FinalArgs F = blockIdx.y ? fb : fa;
    int t = threadIdx.x;
    int tr = t >> 4, tc = t & 15;
    int row0 = blockIdx.x * 128;

    load_weight(F.Wo, sW, t);
    load_atile(F.Hin, sA, t, row0, n);
    __syncthreads();

    float acc[8][8];
#pragma unroll
    for (int i = 0; i < 8; i++)
#pragma unroll
        for (int j = 0; j < 8; j++) acc[i][j] = 0.f;

    gemm_tile(sW, sA, tr, tc, acc);

    float bv[8];
#pragma unroll
    for (int j = 0; j < 8; j++) bv[j] = __ldg(&F.bo[tc * 8 + j]);

#pragma unroll
    for (int i = 0; i < 8; i++) {
        int r = row0 + tr + 16 * i;
        if (r < n) {
            float4 v0, v1;
            v0.x = acc[i][0] + bv[0]; v0.y = acc[i][1] + bv[1];
            v0.z = acc[i][2] + bv[2]; v0.w = acc[i][3] + bv[3];
            v1.x = acc[i][4] + bv[4]; v1.y = acc[i][5] + bv[5];
            v1.z = acc[i][6] + bv[6]; v1.w = acc[i][7] + bv[7];
            ((float4*)F.G)[r * 32 + tc * 2] = v0;
            ((float4*)F.G)[r * 32 + tc * 2 + 1] = v1;
        }
    }
}

// ---------------- LayerNorm: warp per row ----------------
__global__ void ln_kernel(const float* __restrict__ q0, const float* __restrict__ q1,
                          const float* __restrict__ gamma, const float* __restrict__ beta,
                          float* __restrict__ out, int n) {
    int gw = (blockIdx.x * blockDim.x + threadIdx.x) >> 5;
    int lane = threadIdx.x & 31;
    if (gw >= n) return;
    const float* g = blockIdx.y ? q1 : q0;
    float4 v = __ldg(&((const float4*)g)[gw * 32 + lane]);
    float s = v.x + v.y + v.z + v.w;
#pragma unroll
    for (int o = 16; o > 0; o >>= 1) s += __shfl_xor_sync(0xffffffffu, s, o);
    float mean = s * (1.0f / 128.0f);
    float dx = v.x - mean, dy = v.y - mean, dz = v.z - mean, dw = v.w - mean;
    float ss = dx * dx + dy * dy + dz * dz + dw * dw;
#pragma unroll
    for (int o = 16; o > 0; o >>= 1) ss += __shfl_xor_sync(0xffffffffu, ss, o);
    float inv = rsqrtf(ss * (1.0f / 128.0f) + 1e-5f);
    float4 ga = __ldg(&((const float4*)gamma)[lane]);
    float4 be = __ldg(&((const float4*)beta)[lane]);
    float4 o4;
    o4.x = fmaf(dx * inv, ga.x, be.x);
    o4.y = fmaf(dy * inv, ga.y, be.y);
    o4.z = fmaf(dz * inv, ga.z, be.z);
    o4.w = fmaf(dw * inv, ga.w, be.w);
    ((float4*)(out + (size_t)(1 + blockIdx.y) * (size_t)n * DIM))[gw * 32 + lane] = o4;
}

// ---------------- threefry noise + reparameterized sample ----------------
// Reproduces jax.random.normal(jax.random.key(42), (N, D), f32) with the
// threefry_partitionable=True path: bits[f] = o0 ^ o1 where
// (o0, o1) = threefry2x32(key=(0, 42), counter=(hi=0, lo=f)).
__device__ __forceinline__ uint32_t rotl32(uint32_t x, int r) {
    return (x << r) | (x >> (32 - r));
}

__device__ __forceinline__ float bits_to_normal(uint32_t b) {
    // uniform in [nextafter(-1,0), 1)
    uint32_t fb = (b >> 9) | 0x3F800000u;
    float u = __uint_as_float(fb) - 1.0f;          // [0,1)
    const float lo = -0.99999994f;                 // nextafter(-1, 0)
    float v = fmaf(u, 2.0f, lo);                   // (hi - lo) rounds to 2.0f
    v = fmaxf(v, lo);
    // XLA ErfInv f32 (Giles)
    float w = -log1pf(-v * v);
    float p;
    if (w < 5.0f) {
        w -= 2.5f;
        p = 2.81022636e-08f;
        p = fmaf(p, w, 3.43273939e-07f);
        p = fmaf(p, w, -3.5233877e-06f);
        p = fmaf(p, w, -4.39150654e-06f);
        p = fmaf(p, w, 0.00021858087f);
        p = fmaf(p, w, -0.00125372503f);
        p = fmaf(p, w, -0.00417768164f);
        p = fmaf(p, w, 0.246640727f);
        p = fmaf(p, w, 1.50140941f);
    } else {
        w = sqrtf(w) - 3.0f;
        p = -0.000200214257f;
        p = fmaf(p, w, 0.000100950558f);
        p = fmaf(p, w, 0.00134934322f);
        p = fmaf(p, w, -0.00367342844f);
        p = fmaf(p, w, 0.00573950773f);
        p = fmaf(p, w, -0.0076224613f);
        p = fmaf(p, w, 0.00943887047f);
        p = fmaf(p, w, 1.00167406f);
        p = fmaf(p, w, 2.83297682f);
    }
    return 1.41421356237f * (p * v);               // sqrt(2) * erfinv(v)
}

__global__ void sample_kernel(float* __restrict__ out, int total) {
    int f = blockIdx.x * blockDim.x + threadIdx.x;
    if (f >= total) return;
    const uint32_t ks0 = 0u, ks1 = 42u;
    const uint32_t ks2 = ks0 ^ ks1 ^ 0x1BD11BDAu;
    uint32_t x0 = 0u + ks0;
    uint32_t x1 = (uint32_t)f + ks1;
#define TFR(r) { x0 += x1; x1 = rotl32(x1, (r)) ^ x0; }
    TFR(13) TFR(15) TFR(26) TFR(6)   x0 += ks1; x1 += ks2 + 1u;
    TFR(17) TFR(29) TFR(16) TFR(24)  x0 += ks2; x1 += ks0 + 2u;
    TFR(13) TFR(15) TFR(26) TFR(6)   x0 += ks0; x1 += ks1 + 3u;
    TFR(17) TFR(29) TFR(16) TFR(24)  x0 += ks1; x1 += ks2 + 4u;
    TFR(13) TFR(15) TFR(26) TFR(6)   x0 += ks2; x1 += ks0 + 5u;
#undef TFR
    uint32_t bits = x0 ^ x1;
    float eps = bits_to_normal(bits);
    const float* mv = out + total;
    const float* sv = out + 2 * total;
    out[f] = fmaf(eps, sv[f], mv[f]);
}

// ---------------- launch ----------------
extern "C" void kernel_launch(void* const* d_in, const int* in_sizes, int n_in,
                              void* d_out, int out_size) {
    const float* x    = (const float*)d_in[0];
    const int*   esrc = (const int*)d_in[1];
    const int*   edst = (const int*)d_in[2];
    const float* mW1  = (const float*)d_in[3];
    const float* mb1  = (const float*)d_in[4];
    const float* mW2  = (const float*)d_in[5];
    const float* mb2  = (const float*)d_in[6];
    const float* meps = (const float*)d_in[7];
    const float* mWo  = (const float*)d_in[8];
    const float* mbo  = (const float*)d_in[9];
    const float* sW1  = (const float*)d_in[10];
    const float* sb1  = (const float*)d_in[11];
    const float* sW2  = (const float*)d_in[12];
    const float* sb2  = (const float*)d_in[13];
    const float* seps = (const float*)d_in[14];
    const float* sWo  = (const float*)d_in[15];
    const float* sbo  = (const float*)d_in[16];
    const float* lng  = (const float*)d_in[17];
    const float* lnb  = (const float*)d_in[18];

    int n = in_sizes[0] / DIM;
    int e = in_sizes[1];
    int total = n * DIM;
    float* out = (float*)d_out;

    void* p;
    cudaGetSymbolAddress(&p, g_u); float* u0 = (float*)p; float* u1 = u0 + ND;
    cudaGetSymbolAddress(&p, g_h); float* h0 = (float*)p; float* h1 = h0 + ND;
    cudaGetSymbolAddress(&p, g_g); float* q0 = (float*)p; float* q1 = q0 + ND;

    cudaFuncSetAttribute(mlp_kernel, cudaFuncAttributeMaxDynamicSharedMemorySize, 131072);
    cudaFuncSetAttribute(final_kernel, cudaFuncAttributeMaxDynamicSharedMemorySize, 131072);

    // CSR by destination (rebuilt every launch; reused across 3 layers x 2 paths)
    zero_deg_kernel<<<(n + 256) / 256, 256>>>(n);
    hist_kernel<<<(e + 255) / 256, 256>>>(edst, e);
    scan_kernel<<<1, 1024>>>(n);
    fill_kernel<<<(e + 255) / 256, 256>>>(esrc, edst, e);

    int spmm_blocks = (n * 32 + 255) / 256;
    int gx = (n + 127) / 128;
    dim3 g2(gx, 2);

    // layer 0 (both paths share h == x, gather once)
    spmm_kernel<<<spmm_blocks, 256>>>(x, x, meps, seps, 0, u0, u1, 1, n);
    mlp_kernel<<<g2, 256, 131072>>>(
        PathGemm{u0, mW1, mb1, mW2, mb2, h0},
        PathGemm{u1, sW1, sb1, sW2, sb2, h1}, n);
    // layer 1
    spmm_kernel<<<spmm_blocks, 256>>>(h0, h1, meps, seps, 1, u0, u1, 0, n);
    mlp_kernel<<<g2, 256, 131072>>>(
        PathGemm{u0, mW1 + DIM * DIM, mb1 + DIM, mW2 + DIM * DIM, mb2 + DIM, h0},
        PathGemm{u1, sW1 + DIM * DIM, sb1 + DIM, sW2 + DIM * DIM, sb2 + DIM, h1}, n);
    // layer 2
    spmm_kernel<<<spmm_blocks, 256>>>(h0, h1, meps, seps, 2, u0, u1, 0, n);
    mlp_kernel<<<g2, 256, 131072>>>(
        PathGemm{u0, mW1 + 2 * DIM * DIM, mb1 + 2 * DIM, mW2 + 2 * DIM * DIM, mb2 + 2 * DIM, h0},
        PathGemm{u1, sW1 + 2 * DIM * DIM, sb1 + 2 * DIM, sW2 + 2 * DIM * DIM, sb2 + 2 * DIM, h1}, n);

    // final projection + layernorm (writes mean_v at out+total, std_v at out+2*total)
    final_kernel<<<g2, 256, 131072>>>(
        FinalArgs{h0, mWo, mbo, q0},
        FinalArgs{h1, sWo, sbo, q1}, n);
    ln_kernel<<<dim3((n + 7) / 8, 2), 256>>>(q0, q1, lng, lnb, out, n);

    // samples = mean_v + threefry_normal * std_v  (writes out[0:total])
    sample_kernel<<<(total + 255) / 256, 256>>>(out, total);
}

// round 3
// speedup vs baseline: 1.2803x; 1.2803x over previous
#include <cuda_runtime.h>
#include <cuda_bf16.h>
#include <stdint.h>
#include <math.h>

#define DIM   128
#define MAXN  50000
#define MAXE  1600000
#define ND    (MAXN * DIM)

// smem word layout (uint32 units), stride-68 padding for conflict-free frags
#define ASTR  68
#define A_HI  0
#define A_LO  8704            // 128*68
#define B_HI  17408
#define B_LO  26112
#define SMEM_WORDS 34816
#define SMEM_BYTES 139264

// ---------------- device scratch ----------------
__device__ int      g_deg[MAXN + 1];
__device__ int      g_rowptr[MAXN + 1];
__device__ int      g_cursor[MAXN + 1];
__device__ int      g_csrc[MAXE];
__device__ float    g_u[2 * ND];
__device__ float    g_h[2 * ND];
__device__ uint32_t g_wprep[14 * 16384];   // per matrix: hi[8192] ++ lo[8192] (bf16x2 words)

// ---------------- bf16 pack helpers ----------------
__device__ __forceinline__ uint32_t pack2bf(float x, float y) {
    unsigned short sx = __bfloat16_as_ushort(__float2bfloat16(x));
    unsigned short sy = __bfloat16_as_ushort(__float2bfloat16(y));
    return (uint32_t)sx | ((uint32_t)sy << 16);
}
__device__ __forceinline__ float bf_res(float x) {
    return x - __bfloat162float(__float2bfloat16(x));
}

__device__ __forceinline__ void mma_bf16(float* c, uint32_t a0, uint32_t a1, uint32_t a2,
                                         uint32_t a3, uint32_t b0, uint32_t b1) {
    asm volatile(
        "mma.sync.aligned.m16n8k16.row.col.f32.bf16.bf16.f32 "
        "{%0,%1,%2,%3},{%4,%5,%6,%7},{%8,%9},{%0,%1,%2,%3};"
        : "+f"(c[0]), "+f"(c[1]), "+f"(c[2]), "+f"(c[3])
        : "r"(a0), "r"(a1), "r"(a2), "r"(a3), "r"(b0), "r"(b1));
}

// ---------------- weight prep: transpose + bf16 split (K-contiguous col layout) ----------------
struct PrepArgs { const float* src[14]; };

__global__ void prep_kernel(PrepArgs a) {
    const float* W = a.src[blockIdx.x];
    uint32_t* dhi = g_wprep + blockIdx.x * 16384;
    uint32_t* dlo = dhi + 8192;
    for (int idx = threadIdx.x; idx < 8192; idx += blockDim.x) {
        int nrow = idx >> 6, kp = idx & 63, k = kp * 2;
        float v0 = __ldg(&W[k * 128 + nrow]);        // Wt[n][k] = W[k][n]
        float v1 = __ldg(&W[(k + 1) * 128 + nrow]);
        dhi[idx] = pack2bf(v0, v1);
        dlo[idx] = pack2bf(bf_res(v0), bf_res(v1));
    }
}

// ---------------- CSR build ----------------
__global__ void zero_deg_kernel(int n) {
    int i = blockIdx.x * blockDim.x + threadIdx.x;
    if (i <= n) g_deg[i] = 0;
}
__global__ void hist_kernel(const int* __restrict__ dst, int e) {
    int i = blockIdx.x * blockDim.x + threadIdx.x;
    if (i < e) atomicAdd(&g_deg[dst[i]], 1);
}
__global__ void scan_kernel(int n) {
    __shared__ int sd[1024];
    int t = threadIdx.x;
    int items = (n + 1023) >> 10;
    int base = t * items;
    int s = 0;
    for (int i = 0; i < items; i++) {
        int idx = base + i;
        if (idx < n) s += g_deg[idx];
    }
    sd[t] = s;
    __syncthreads();
    for (int o = 1; o < 1024; o <<= 1) {
        int v = (t >= o) ? sd[t - o] : 0;
        __syncthreads();
        sd[t] += v;
        __syncthreads();
    }
    int run = (t == 0) ? 0 : sd[t - 1];
    for (int i = 0; i < items; i++) {
        int idx = base + i;
        if (idx < n) {
            g_rowptr[idx] = run;
            g_cursor[idx] = run;
            run += g_deg[idx];
            if (idx == n - 1) g_rowptr[n] = run;
        }
    }
}
__global__ void fill_kernel(const int* __restrict__ src, const int* __restrict__ dst, int e) {
    int i = blockIdx.x * blockDim.x + threadIdx.x;
    if (i < e) {
        int p = atomicAdd(&g_cursor[dst[i]], 1);
        g_csrc[p] = src[i];
    }
}

// ---------------- SpMM + combine ----------------
__global__ void spmm_kernel(const float* __restrict__ hm, const float* __restrict__ hs,
                            const float* __restrict__ epsm, const float* __restrict__ epss,
                            int layer, float* __restrict__ um, float* __restrict__ us,
                            int same, int n) {
    int gw = (blockIdx.x * blockDim.x + threadIdx.x) >> 5;
    int lane = threadIdx.x & 31;
    if (gw >= n) return;
    int rp0 = g_rowptr[gw], rp1 = g_rowptr[gw + 1];
    const float4* hm4 = (const float4*)hm;
    const float4* hs4 = (const float4*)hs;
    float4 am = make_float4(0.f, 0.f, 0.f, 0.f);
    float4 as = make_float4(0.f, 0.f, 0.f, 0.f);
#pragma unroll 2
    for (int j = rp0; j < rp1; ++j) {
        int s = __ldg(&g_csrc[j]);
        float4 v = __ldg(&hm4[s * 32 + lane]);
        am.x += v.x; am.y += v.y; am.z += v.z; am.w += v.w;
        if (!same) {
            float4 w = __ldg(&hs4[s * 32 + lane]);
            as.x += w.x; as.y += w.y; as.z += w.z; as.w += w.w;
        }
    }
    if (same) as = am;
    float cm = 1.0f + __ldg(&epsm[layer]);
    float cs = 1.0f + __ldg(&epss[layer]);
    float4 h0m = __ldg(&hm4[gw * 32 + lane]);
    float4 h0s = same ? h0m : __ldg(&hs4[gw * 32 + lane]);
    float4 om, os;
    om.x = fmaf(cm, h0m.x, am.x); om.y = fmaf(cm, h0m.y, am.y);
    om.z = fmaf(cm, h0m.z, am.z); om.w = fmaf(cm, h0m.w, am.w);
    os.x = fmaf(cs, h0s.x, as.x); os.y = fmaf(cs, h0s.y, as.y);
    os.z = fmaf(cs, h0s.z, as.z); os.w = fmaf(cs, h0s.w, as.w);
    ((float4*)um)[gw * 32 + lane] = om;
    ((float4*)us)[gw * 32 + lane] = os;
}

// ---------------- shared GEMM pieces ----------------
// Load 128 U rows, fp32 -> bf16 hi/lo into smem A (all 256 threads)
__device__ __forceinline__ void load_A_bf(const float* __restrict__ U, int row0, int n,
                                          uint32_t* smw, int t) {
    int row = t >> 1, half = t & 1;
    int r = row0 + row;
    const float4* u4 = (const float4*)U + (size_t)r * 32 + half * 16;
    uint32_t* ah = smw + A_HI + row * ASTR + half * 32;
    uint32_t* al = smw + A_LO + row * ASTR + half * 32;
#pragma unroll 4
    for (int q = 0; q < 16; q++) {
        float4 v = make_float4(0.f, 0.f, 0.f, 0.f);
        if (r < n) v = __ldg(&u4[q]);
        ah[q * 2]     = pack2bf(v.x, v.y);
        al[q * 2]     = pack2bf(bf_res(v.x), bf_res(v.y));
        ah[q * 2 + 1] = pack2bf(v.z, v.w);
        al[q * 2 + 1] = pack2bf(bf_res(v.z), bf_res(v.w));
    }
}

// Copy prepped weight (hi 8192 words ++ lo 8192 words) into smem B with stride pad
__device__ __forceinline__ void copy_W(const uint32_t* __restrict__ Wp, uint32_t* smw, int t) {
    const uint4* s4 = (const uint4*)Wp;   // 4096 uint4: hi 0..2047, lo 2048..4095
#pragma unroll
    for (int i = 0; i < 8; i++) {
        int j = t + i * 256;
        int nrow = j >> 4, kp = (j & 15) * 4;
        *(uint4*)(smw + B_HI + nrow * ASTR + kp) = __ldg(&s4[j]);
        *(uint4*)(smw + B_LO + nrow * ASTR + kp) = __ldg(&s4[j + 2048]);
    }
}

__device__ __forceinline__ void gemm_pass(const uint32_t* __restrict__ smw, int aoff, int boff,
                                          float acc[2][8][4], int ra, int kq, int nb) {
#pragma unroll
    for (int kk = 0; kk < 8; kk++) {
        int kp0 = kk * 8 + kq, kp1 = kp0 + 4;
        uint32_t a[2][4];
#pragma unroll
        for (int i = 0; i < 2; i++) {
            int rb = aoff + (ra + i * 16) * ASTR;
            a[i][0] = smw[rb + kp0];
            a[i][1] = smw[rb + 8 * ASTR + kp0];
            a[i][2] = smw[rb + kp1];
            a[i][3] = smw[rb + 8 * ASTR + kp1];
        }
#pragma unroll
        for (int j = 0; j < 8; j++) {
            int bb = boff + (nb + j * 8) * ASTR;
            uint32_t b0 = smw[bb + kp0], b1 = smw[bb + kp1];
            mma_bf16(acc[0][j], a[0][0], a[0][1], a[0][2], a[0][3], b0, b1);
            mma_bf16(acc[1][j], a[1][0], a[1][1], a[1][2], a[1][3], b0, b1);
        }
    }
}

__device__ __forceinline__ void gemm3(const uint32_t* smw, float acc[2][8][4],
                                      int ra, int kq, int nb) {
    gemm_pass(smw, A_HI, B_HI, acc, ra, kq, nb);
    gemm_pass(smw, A_HI, B_LO, acc, ra, kq, nb);
    gemm_pass(smw, A_LO, B_HI, acc, ra, kq, nb);
}

__device__ __forceinline__ void zero_acc(float acc[2][8][4]) {
#pragma unroll
    for (int i = 0; i < 2; i++)
#pragma unroll
        for (int j = 0; j < 8; j++)
#pragma unroll
            for (int q = 0; q < 4; q++) acc[i][j][q] = 0.f;
}

__device__ __forceinline__ float sigf(float x) { return 1.0f / (1.0f + expf(-x)); }

// ---------------- MLP layer: H = sigmoid(U@W1+b1)@W2 + b2 ----------------
struct MlpP { const float* U; const uint32_t* W1p; const uint32_t* W2p;
              const float* b1; const float* b2; float* H; };

__global__ __launch_bounds__(256, 1) void mlp_mma_kernel(MlpP pm, MlpP ps, int n) {
    extern __shared__ uint32_t smw[];
    MlpP P = blockIdx.y ? ps : pm;
    int row0 = blockIdx.x * 128;
    int t = threadIdx.x, lane = t & 31, wid = t >> 5;
    int wm = wid >> 1, wn = wid & 1;
    int ra = wm * 32 + (lane >> 2);
    int kq = lane & 3;
    int nb = wn * 64 + (lane >> 2);

    load_A_bf(P.U, row0, n, smw, t);
    copy_W(P.W1p, smw, t);
    __syncthreads();

    float acc[2][8][4];
    zero_acc(acc);
    gemm3(smw, acc, ra, kq, nb);
    __syncthreads();   // all reads of A/B done before rewrite

    // epilogue 1: sigmoid(C + b1) -> A tile (hi/lo), in fragment layout
#pragma unroll
    for (int i = 0; i < 2; i++) {
#pragma unroll
        for (int j = 0; j < 8; j++) {
            int rl = wm * 32 + i * 16 + (lane >> 2);
            int c0 = wn * 64 + j * 8 + 2 * kq;
            float s0 = sigf(acc[i][j][0] + __ldg(&P.b1[c0]));
            float s1 = sigf(acc[i][j][1] + __ldg(&P.b1[c0 + 1]));
            float s2 = sigf(acc[i][j][2] + __ldg(&P.b1[c0]));
            float s3 = sigf(acc[i][j][3] + __ldg(&P.b1[c0 + 1]));
            int kp = wn * 32 + j * 4 + kq;
            smw[A_HI + rl * ASTR + kp] = pack2bf(s0, s1);
            smw[A_LO + rl * ASTR + kp] = pack2bf(bf_res(s0), bf_res(s1));
            smw[A_HI + (rl + 8) * ASTR + kp] = pack2bf(s2, s3);
            smw[A_LO + (rl + 8) * ASTR + kp] = pack2bf(bf_res(s2), bf_res(s3));
        }
    }
    copy_W(P.W2p, smw, t);
    __syncthreads();

    zero_acc(acc);
    gemm3(smw, acc, ra, kq, nb);

    // epilogue 2: H = C + b2
#pragma unroll
    for (int i = 0; i < 2; i++) {
#pragma unroll
        for (int j = 0; j < 8; j++) {
            int gr = row0 + wm * 32 + i * 16 + (lane >> 2);
            int c0 = wn * 64 + j * 8 + 2 * kq;
            float bb0 = __ldg(&P.b2[c0]), bb1 = __ldg(&P.b2[c0 + 1]);
            if (gr < n) {
                float2 v = make_float2(acc[i][j][0] + bb0, acc[i][j][1] + bb1);
                *(float2*)(P.H + (size_t)gr * DIM + c0) = v;
            }
            if (gr + 8 < n) {
                float2 v = make_float2(acc[i][j][2] + bb0, acc[i][j][3] + bb1);
                *(float2*)(P.H + (size_t)(gr + 8) * DIM + c0) = v;
            }
        }
    }
}

// ---------------- final: LN(Hin @ Wout + bout) ----------------
struct FinP { const float* Hin; const uint32_t* Wp; const float* bo; };

__global__ __launch_bounds__(256, 1) void final_mma_kernel(FinP pm, FinP ps,
                                                           const float* __restrict__ gamma,
                                                           const float* __restrict__ beta,
                                                           float* __restrict__ out, int n) {
    extern __shared__ uint32_t smw[];
    FinP P = blockIdx.y ? ps : pm;
    int row0 = blockIdx.x * 128;
    int t = threadIdx.x, lane = t & 31, wid = t >> 5;
    int wm = wid >> 1, wn = wid & 1;
    int ra = wm * 32 + (lane >> 2);
    int kq = lane & 3;
    int nb = wn * 64 + (lane >> 2);

    load_A_bf(P.Hin, row0, n, smw, t);
    copy_W(P.Wp, smw, t);
    __syncthreads();

    float acc[2][8][4];
    zero_acc(acc);
    gemm3(smw, acc, ra, kq, nb);
    __syncthreads();   // done reading A region; reuse as staging

    // stage C + bo into smem float grid, stride 133 (conflict-free row reads)
    float* gS = (float*)smw;
#pragma unroll
    for (int i = 0; i < 2; i++) {
#pragma unroll
        for (int j = 0; j < 8; j++) {
            int rl = wm * 32 + i * 16 + (lane >> 2);
            int c0 = wn * 64 + j * 8 + 2 * kq;
            float bb0 = __ldg(&P.bo[c0]), bb1 = __ldg(&P.bo[c0 + 1]);
            gS[rl * 133 + c0]       = acc[i][j][0] + bb0;
            gS[rl * 133 + c0 + 1]   = acc[i][j][1] + bb1;
            gS[(rl + 8) * 133 + c0]     = acc[i][j][2] + bb0;
            gS[(rl + 8) * 133 + c0 + 1] = acc[i][j][3] + bb1;
        }
    }
    __syncthreads();

    if (t < 128) {
        int r = row0 + t;
        if (r < n) {
            const float* rowp = gS + t * 133;
            float sum = 0.f;
#pragma unroll 8
            for (int c = 0; c < 128; c++) sum += rowp[c];
            float mean = sum * (1.0f / 128.0f);
            float ss = 0.f;
#pragma unroll 8
            for (int c = 0; c < 128; c++) {
                float d = rowp[c] - mean;
                ss += d * d;
            }
            float inv = rsqrtf(ss * (1.0f / 128.0f) + 1e-5f);
            float* op = out + (size_t)(1 + blockIdx.y) * (size_t)n * DIM + (size_t)r * DIM;
#pragma unroll 4
            for (int c = 0; c < 128; c += 4) {
                float4 o;
                o.x = fmaf((rowp[c]     - mean) * inv, __ldg(&gamma[c]),     __ldg(&beta[c]));
                o.y = fmaf((rowp[c + 1] - mean) * inv, __ldg(&gamma[c + 1]), __ldg(&beta[c + 1]));
                o.z = fmaf((rowp[c + 2] - mean) * inv, __ldg(&gamma[c + 2]), __ldg(&beta[c + 2]));
                o.w = fmaf((rowp[c + 3] - mean) * inv, __ldg(&gamma[c + 3]), __ldg(&beta[c + 3]));
                *(float4*)(op + c) = o;
            }
        }
    }
}

// ---------------- threefry noise + reparameterized sample ----------------
__device__ __forceinline__ uint32_t rotl32(uint32_t x, int r) {
    return (x << r) | (x >> (32 - r));
}
__device__ __forceinline__ float bits_to_normal(uint32_t b) {
    uint32_t fb = (b >> 9) | 0x3F800000u;
    float u = __uint_as_float(fb) - 1.0f;
    const float lo = -0.99999994f;
    float v = fmaf(u, 2.0f, lo);
    v = fmaxf(v, lo);
    float w = -log1pf(-v * v);
    float p;
    if (w < 5.0f) {
        w -= 2.5f;
        p = 2.81022636e-08f;
        p = fmaf(p, w, 3.43273939e-07f);
        p = fmaf(p, w, -3.5233877e-06f);
        p = fmaf(p, w, -4.39150654e-06f);
        p = fmaf(p, w, 0.00021858087f);
        p = fmaf(p, w, -0.00125372503f);
        p = fmaf(p, w, -0.00417768164f);
        p = fmaf(p, w, 0.246640727f);
        p = fmaf(p, w, 1.50140941f);
    } else {
        w = sqrtf(w) - 3.0f;
        p = -0.000200214257f;
        p = fmaf(p, w, 0.000100950558f);
        p = fmaf(p, w, 0.00134934322f);
        p = fmaf(p, w, -0.00367342844f);
        p = fmaf(p, w, 0.00573950773f);
        p = fmaf(p, w, -0.0076224613f);
        p = fmaf(p, w, 0.00943887047f);
        p = fmaf(p, w, 1.00167406f);
        p = fmaf(p, w, 2.83297682f);
    }
    return 1.41421356237f * (p * v);
}

__global__ void sample_kernel(float* __restrict__ out, int total) {
    int f = blockIdx.x * blockDim.x + threadIdx.x;
    if (f >= total) return;
    const uint32_t ks0 = 0u, ks1 = 42u;
    const uint32_t ks2 = ks0 ^ ks1 ^ 0x1BD11BDAu;
    uint32_t x0 = 0u + ks0;
    uint32_t x1 = (uint32_t)f + ks1;
#define TFR(r) { x0 += x1; x1 = rotl32(x1, (r)) ^ x0; }
    TFR(13) TFR(15) TFR(26) TFR(6)   x0 += ks1; x1 += ks2 + 1u;
    TFR(17) TFR(29) TFR(16) TFR(24)  x0 += ks2; x1 += ks0 + 2u;
    TFR(13) TFR(15) TFR(26) TFR(6)   x0 += ks0; x1 += ks1 + 3u;
    TFR(17) TFR(29) TFR(16) TFR(24)  x0 += ks1; x1 += ks2 + 4u;
    TFR(13) TFR(15) TFR(26) TFR(6)   x0 += ks2; x1 += ks0 + 5u;
#undef TFR
    uint32_t bits = x0 ^ x1;
    float eps = bits_to_normal(bits);
    const float* mv = out + total;
    const float* sv = out + 2 * total;
    out[f] = fmaf(eps, sv[f], mv[f]);
}

// ---------------- launch ----------------
extern "C" void kernel_launch(void* const* d_in, const int* in_sizes, int n_in,
                              void* d_out, int out_size) {
    const float* x    = (const float*)d_in[0];
    const int*   esrc = (const int*)d_in[1];
    const int*   edst = (const int*)d_in[2];
    const float* mW1  = (const float*)d_in[3];
    const float* mb1  = (const float*)d_in[4];
    const float* mW2  = (const float*)d_in[5];
    const float* mb2  = (const float*)d_in[6];
    const float* meps = (const float*)d_in[7];
    const float* mWo  = (const float*)d_in[8];
    const float* mbo  = (const float*)d_in[9];
    const float* sW1  = (const float*)d_in[10];
    const float* sb1  = (const float*)d_in[11];
    const float* sW2  = (const float*)d_in[12];
    const float* sb2  = (const float*)d_in[13];
    const float* seps = (const float*)d_in[14];
    const float* sWo  = (const float*)d_in[15];
    const float* sbo  = (const float*)d_in[16];
    const float* lng  = (const float*)d_in[17];
    const float* lnb  = (const float*)d_in[18];

    int n = in_sizes[0] / DIM;
    int e = in_sizes[1];
    int total = n * DIM;
    float* out = (float*)d_out;

    void* p;
    cudaGetSymbolAddress(&p, g_u); float* u0 = (float*)p; float* u1 = u0 + ND;
    cudaGetSymbolAddress(&p, g_h); float* h0 = (float*)p; float* h1 = h0 + ND;
    cudaGetSymbolAddress(&p, g_wprep); uint32_t* wp = (uint32_t*)p;

    cudaFuncSetAttribute(mlp_mma_kernel, cudaFuncAttributeMaxDynamicSharedMemorySize, SMEM_BYTES);
    cudaFuncSetAttribute(final_mma_kernel, cudaFuncAttributeMaxDynamicSharedMemorySize, SMEM_BYTES);

    // weight prep (slot = path*7 + layer*2 + mat ; Wout at path*7+6)
    PrepArgs pa;
    for (int pth = 0; pth < 2; pth++) {
        const float* W1 = pth ? sW1 : mW1;
        const float* W2 = pth ? sW2 : mW2;
        const float* Wo = pth ? sWo : mWo;
        for (int l = 0; l < 3; l++) {
            pa.src[pth * 7 + l * 2 + 0] = W1 + l * 16384;
            pa.src[pth * 7 + l * 2 + 1] = W2 + l * 16384;
        }
        pa.src[pth * 7 + 6] = Wo;
    }
    prep_kernel<<<14, 256>>>(pa);

    // CSR by destination
    zero_deg_kernel<<<(n + 256) / 256, 256>>>(n);
    hist_kernel<<<(e + 255) / 256, 256>>>(edst, e);
    scan_kernel<<<1, 1024>>>(n);
    fill_kernel<<<(e + 255) / 256, 256>>>(esrc, edst, e);

    int spmm_blocks = (n * 32 + 255) / 256;
    int gx = (n + 127) / 128;
    dim3 g2(gx, 2);

    for (int l = 0; l < 3; l++) {
        const float* hm_in = (l == 0) ? x : h0;
        const float* hs_in = (l == 0) ? x : h1;
        spmm_kernel<<<spmm_blocks, 256>>>(hm_in, hs_in, meps, seps, l, u0, u1, l == 0, n);
        MlpP pmm{u0, wp + (0 * 7 + 2 * l) * 16384, wp + (0 * 7 + 2 * l + 1) * 16384,
                 mb1 + l * DIM, mb2 + l * DIM, h0};
        MlpP pss{u1, wp + (1 * 7 + 2 * l) * 16384, wp + (1 * 7 + 2 * l + 1) * 16384,
                 sb1 + l * DIM, sb2 + l * DIM, h1};
        mlp_mma_kernel<<<g2, 256, SMEM_BYTES>>>(pmm, pss, n);
    }

    FinP fm{h0, wp + 6 * 16384, mbo};
    FinP fs{h1, wp + 13 * 16384, sbo};
    final_mma_kernel<<<g2, 256, SMEM_BYTES>>>(fm, fs, lng, lnb, out, n);

    sample_kernel<<<(total + 255) / 256, 256>>>(out, total);
}

// round 5
// speedup vs baseline: 1.3986x; 1.0924x over previous
#include <cuda_runtime.h>
#include <cuda_bf16.h>
#include <stdint.h>
#include <math.h>

#define DIM   128
#define MAXN  50000
#define MAXE  1600000
#define ND    (MAXN * DIM)

// smem word layout (uint32 units), stride-68 padding for conflict-free frags
#define ASTR  68
#define A_HI  0
#define A_LO  8704            // 128*68
#define B_HI  17408
#define B_LO  26112
#define SMEM_WORDS 34816
#define SMEM_BYTES 139264

#define SCAN_BLK 1024
#define MAX_PARTS 64

// ---------------- device scratch ----------------
__device__ int      g_deg[MAXN + 1];
__device__ int      g_rowptr[MAXN + 1];
__device__ int      g_cursor[MAXN + 1];
__device__ int      g_part[MAX_PARTS];
__device__ int      g_csrc[MAXE];
__device__ float    g_u[2 * ND];
__device__ float    g_h[2 * ND];
__device__ uint32_t g_wprep[14 * 16384];   // per matrix: hi[8192] ++ lo[8192] (bf16x2 words)

// ---------------- bf16 pack helpers ----------------
__device__ __forceinline__ uint32_t pack2bf(float x, float y) {
    unsigned short sx = __bfloat16_as_ushort(__float2bfloat16(x));
    unsigned short sy = __bfloat16_as_ushort(__float2bfloat16(y));
    return (uint32_t)sx | ((uint32_t)sy << 16);
}
__device__ __forceinline__ float bf_res(float x) {
    return x - __bfloat162float(__float2bfloat16(x));
}

__device__ __forceinline__ void mma_bf16(float* c, uint32_t a0, uint32_t a1, uint32_t a2,
                                         uint32_t a3, uint32_t b0, uint32_t b1) {
    asm volatile(
        "mma.sync.aligned.m16n8k16.row.col.f32.bf16.bf16.f32 "
        "{%0,%1,%2,%3},{%4,%5,%6,%7},{%8,%9},{%0,%1,%2,%3};"
        : "+f"(c[0]), "+f"(c[1]), "+f"(c[2]), "+f"(c[3])
        : "r"(a0), "r"(a1), "r"(a2), "r"(a3), "r"(b0), "r"(b1));
}

// ---------------- weight prep: coalesced transpose + bf16 split ----------------
struct PrepArgs { const float* src[14]; };

__global__ void prep_kernel(PrepArgs a) {
    extern __shared__ float tile[];          // 128 x 130
    const float* W = a.src[blockIdx.x];
    uint32_t* dhi = g_wprep + blockIdx.x * 16384;
    uint32_t* dlo = dhi + 8192;
    // coalesced load of W[k][n] -> tile[n][k]
    for (int idx = threadIdx.x; idx < 16384; idx += blockDim.x) {
        int k = idx >> 7, nc = idx & 127;
        tile[nc * 130 + k] = __ldg(&W[idx]);
    }
    __syncthreads();
    for (int idx = threadIdx.x; idx < 8192; idx += blockDim.x) {
        int nrow = idx >> 6, kp = idx & 63;
        float v0 = tile[nrow * 130 + kp * 2];
        float v1 = tile[nrow * 130 + kp * 2 + 1];
        dhi[idx] = pack2bf(v0, v1);
        dlo[idx] = pack2bf(bf_res(v0), bf_res(v1));
    }
}

// ---------------- CSR build ----------------
__global__ void zero_deg_kernel(int n) {
    int i = blockIdx.x * blockDim.x + threadIdx.x;
    if (i <= n) g_deg[i] = 0;
}
__global__ void hist_kernel(const int* __restrict__ dst, int e) {
    int i = blockIdx.x * blockDim.x + threadIdx.x;
    if (i < e) atomicAdd(&g_deg[dst[i]], 1);
}

// phase 1: per-block sum of its 1024-chunk
__global__ void scan_p1(int n) {
    __shared__ int sd[32];
    int i = blockIdx.x * SCAN_BLK + threadIdx.x;
    int v = (i < n) ? g_deg[i] : 0;
#pragma unroll
    for (int o = 16; o > 0; o >>= 1) v += __shfl_xor_sync(0xffffffffu, v, o);
    if ((threadIdx.x & 31) == 0) sd[threadIdx.x >> 5] = v;
    __syncthreads();
    if (threadIdx.x < 32) {
        int s = sd[threadIdx.x];
#pragma unroll
        for (int o = 16; o > 0; o >>= 1) s += __shfl_xor_sync(0xffffffffu, s, o);
        if (threadIdx.x == 0) g_part[blockIdx.x] = s;
    }
}
// phase 2: exclusive scan of <= MAX_PARTS partials, single warp, 2 per thread
__global__ void scan_p2(int nb) {
    int t = threadIdx.x;                       // 0..31
    int v0 = (2 * t < nb) ? g_part[2 * t] : 0;
    int v1 = (2 * t + 1 < nb) ? g_part[2 * t + 1] : 0;
    int s = v0 + v1;
    int incl = s;
#pragma unroll
    for (int o = 1; o < 32; o <<= 1) {
        int u = __shfl_up_sync(0xffffffffu, incl, o);
        if (t >= o) incl += u;
    }
    int excl = incl - s;
    if (2 * t < MAX_PARTS) g_part[2 * t] = excl;
    if (2 * t + 1 < MAX_PARTS) g_part[2 * t + 1] = excl + v0;
}
// phase 3: block exclusive scan + offset, write rowptr & cursor
__global__ void scan_p3(int n) {
    __shared__ int sw[32];
    int b = blockIdx.x, t = threadIdx.x;
    int i = b * SCAN_BLK + t;
    int v = (i < n) ? g_deg[i] : 0;
    int lane = t & 31, w = t >> 5;
    int incl = v;
#pragma unroll
    for (int o = 1; o < 32; o <<= 1) {
        int u = __shfl_up_sync(0xffffffffu, incl, o);
        if (lane >= o) incl += u;
    }
    if (lane == 31) sw[w] = incl;
    __syncthreads();
    if (t < 32) {
        int s = sw[t];
        int si = s;
#pragma unroll
        for (int o = 1; o < 32; o <<= 1) {
            int u = __shfl_up_sync(0xffffffffu, si, o);
            if (t >= o) si += u;
        }
        sw[t] = si - s;   // exclusive warp offsets
    }
    __syncthreads();
    int excl = incl - v + sw[w] + g_part[b];
    if (i < n) {
        g_rowptr[i] = excl;
        g_cursor[i] = excl;
        if (i == n - 1) g_rowptr[n] = excl + v;
    }
}

__global__ void fill_kernel(const int* __restrict__ src, const int* __restrict__ dst, int e) {
    int i = blockIdx.x * blockDim.x + threadIdx.x;
    if (i < e) {
        int p = atomicAdd(&g_cursor[dst[i]], 1);
        g_csrc[p] = src[i];
    }
}

// ---------------- SpMM + combine ----------------
__global__ void spmm_kernel(const float* __restrict__ hm, const float* __restrict__ hs,
                            const float* __restrict__ epsm, const float* __restrict__ epss,
                            int layer, float* __restrict__ um, float* __restrict__ us,
                            int same, int n) {
    int gw = (blockIdx.x * blockDim.x + threadIdx.x) >> 5;
    int lane = threadIdx.x & 31;
    if (gw >= n) return;
    int rp0 = g_rowptr[gw], rp1 = g_rowptr[gw + 1];
    const float4* hm4 = (const float4*)hm;
    const float4* hs4 = (const float4*)hs;
    float4 am = make_float4(0.f, 0.f, 0.f, 0.f);
    float4 as = make_float4(0.f, 0.f, 0.f, 0.f);
#pragma unroll 2
    for (int j = rp0; j < rp1; ++j) {
        int s = __ldg(&g_csrc[j]);
        float4 v = __ldg(&hm4[s * 32 + lane]);
        am.x += v.x; am.y += v.y; am.z += v.z; am.w += v.w;
        if (!same) {
            float4 w = __ldg(&hs4[s * 32 + lane]);
            as.x += w.x; as.y += w.y; as.z += w.z; as.w += w.w;
        }
    }
    if (same) as = am;
    float cm = 1.0f + __ldg(&epsm[layer]);
    float cs = 1.0f + __ldg(&epss[layer]);
    float4 h0m = __ldg(&hm4[gw * 32 + lane]);
    float4 h0s = same ? h0m : __ldg(&hs4[gw * 32 + lane]);
    float4 om, os;
    om.x = fmaf(cm, h0m.x, am.x); om.y = fmaf(cm, h0m.y, am.y);
    om.z = fmaf(cm, h0m.z, am.z); om.w = fmaf(cm, h0m.w, am.w);
    os.x = fmaf(cs, h0s.x, as.x); os.y = fmaf(cs, h0s.y, as.y);
    os.z = fmaf(cs, h0s.z, as.z); os.w = fmaf(cs, h0s.w, as.w);
    ((float4*)um)[gw * 32 + lane] = om;
    ((float4*)us)[gw * 32 + lane] = os;
}

// ---------------- shared GEMM pieces ----------------
__device__ __forceinline__ void load_A_bf(const float* __restrict__ U, int row0, int n,
                                          uint32_t* smw, int t) {
    int row = t >> 1, half = t & 1;
    int r = row0 + row;
    const float4* u4 = (const float4*)U + (size_t)r * 32 + half * 16;
    uint32_t* ah = smw + A_HI + row * ASTR + half * 32;
    uint32_t* al = smw + A_LO + row * ASTR + half * 32;
#pragma unroll 4
    for (int q = 0; q < 16; q++) {
        float4 v = make_float4(0.f, 0.f, 0.f, 0.f);
        if (r < n) v = __ldg(&u4[q]);
        ah[q * 2]     = pack2bf(v.x, v.y);
        al[q * 2]     = pack2bf(bf_res(v.x), bf_res(v.y));
        ah[q * 2 + 1] = pack2bf(v.z, v.w);
        al[q * 2 + 1] = pack2bf(bf_res(v.z), bf_res(v.w));
    }
}

__device__ __forceinline__ void copy_W(const uint32_t* __restrict__ Wp, uint32_t* smw, int t) {
    const uint4* s4 = (const uint4*)Wp;
#pragma unroll
    for (int i = 0; i < 8; i++) {
        int j = t + i * 256;
        int nrow = j >> 4, kp = (j & 15) * 4;
        *(uint4*)(smw + B_HI + nrow * ASTR + kp) = __ldg(&s4[j]);
        *(uint4*)(smw + B_LO + nrow * ASTR + kp) = __ldg(&s4[j + 2048]);
    }
}

__device__ __forceinline__ void gemm_pass(const uint32_t* __restrict__ smw, int aoff, int boff,
                                          float acc[2][8][4], int ra, int kq, int nb) {
#pragma unroll
    for (int kk = 0; kk < 8; kk++) {
        int kp0 = kk * 8 + kq, kp1 = kp0 + 4;
        uint32_t a[2][4];
#pragma unroll
        for (int i = 0; i < 2; i++) {
            int rb = aoff + (ra + i * 16) * ASTR;
            a[i][0] = smw[rb + kp0];
            a[i][1] = smw[rb + 8 * ASTR + kp0];
            a[i][2] = smw[rb + kp1];
            a[i][3] = smw[rb + 8 * ASTR + kp1];
        }
#pragma unroll
        for (int j = 0; j < 8; j++) {
            int bb = boff + (nb + j * 8) * ASTR;
            uint32_t b0 = smw[bb + kp0], b1 = smw[bb + kp1];
            mma_bf16(acc[0][j], a[0][0], a[0][1], a[0][2], a[0][3], b0, b1);
            mma_bf16(acc[1][j], a[1][0], a[1][1], a[1][2], a[1][3], b0, b1);
        }
    }
}

__device__ __forceinline__ void gemm3(const uint32_t* smw, float acc[2][8][4],
                                      int ra, int kq, int nb) {
    gemm_pass(smw, A_HI, B_HI, acc, ra, kq, nb);
    gemm_pass(smw, A_HI, B_LO, acc, ra, kq, nb);
    gemm_pass(smw, A_LO, B_HI, acc, ra, kq, nb);
}

__device__ __forceinline__ void zero_acc(float acc[2][8][4]) {
#pragma unroll
    for (int i = 0; i < 2; i++)
#pragma unroll
        for (int j = 0; j < 8; j++)
#pragma unroll
            for (int q = 0; q < 4; q++) acc[i][j][q] = 0.f;
}

__device__ __forceinline__ float sigf(float x) { return 1.0f / (1.0f + expf(-x)); }

// ---------------- MLP layer: H = sigmoid(U@W1+b1)@W2 + b2 ----------------
struct MlpP { const float* U; const uint32_t* W1p; const uint32_t* W2p;
              const float* b1; const float* b2; float* H; };

__global__ __launch_bounds__(256, 1) void mlp_mma_kernel(MlpP pm, MlpP ps, int n) {
    extern __shared__ uint32_t smw[];
    MlpP P = blockIdx.y ? ps : pm;
    int row0 = blockIdx.x * 128;
    int t = threadIdx.x, lane = t & 31, wid = t >> 5;
    int wm = wid >> 1, wn = wid & 1;
    int ra = wm * 32 + (lane >> 2);
    int kq = lane & 3;
    int nb = wn * 64 + (lane >> 2);

    load_A_bf(P.U, row0, n, smw, t);
    copy_W(P.W1p, smw, t);
    __syncthreads();

    float acc[2][8][4];
    zero_acc(acc);
    gemm3(smw, acc, ra, kq, nb);
    __syncthreads();

    // epilogue 1: sigmoid(C + b1) -> A tile (hi/lo), in fragment layout
#pragma unroll
    for (int i = 0; i < 2; i++) {
#pragma unroll
        for (int j = 0; j < 8; j++) {
            int rl = wm * 32 + i * 16 + (lane >> 2);
            int c0 = wn * 64 + j * 8 + 2 * kq;
            float s0 = sigf(acc[i][j][0] + __ldg(&P.b1[c0]));
            float s1 = sigf(acc[i][j][1] + __ldg(&P.b1[c0 + 1]));
            float s2 = sigf(acc[i][j][2] + __ldg(&P.b1[c0]));
            float s3 = sigf(acc[i][j][3] + __ldg(&P.b1[c0 + 1]));
            int kp = wn * 32 + j * 4 + kq;
            smw[A_HI + rl * ASTR + kp] = pack2bf(s0, s1);
            smw[A_LO + rl * ASTR + kp] = pack2bf(bf_res(s0), bf_res(s1));
            smw[A_HI + (rl + 8) * ASTR + kp] = pack2bf(s2, s3);
            smw[A_LO + (rl + 8) * ASTR + kp] = pack2bf(bf_res(s2), bf_res(s3));
        }
    }
    copy_W(P.W2p, smw, t);
    __syncthreads();

    zero_acc(acc);
    gemm3(smw, acc, ra, kq, nb);

    // epilogue 2: H = C + b2
#pragma unroll
    for (int i = 0; i < 2; i++) {
#pragma unroll
        for (int j = 0; j < 8; j++) {
            int gr = row0 + wm * 32 + i * 16 + (lane >> 2);
            int c0 = wn * 64 + j * 8 + 2 * kq;
            float bb0 = __ldg(&P.b2[c0]), bb1 = __ldg(&P.b2[c0 + 1]);
            if (gr < n) {
                float2 v = make_float2(acc[i][j][0] + bb0, acc[i][j][1] + bb1);
                *(float2*)(P.H + (size_t)gr * DIM + c0) = v;
            }
            if (gr + 8 < n) {
                float2 v = make_float2(acc[i][j][2] + bb0, acc[i][j][3] + bb1);
                *(float2*)(P.H + (size_t)(gr + 8) * DIM + c0) = v;
            }
        }
    }
}

// ---------------- final: LN(Hin @ Wout + bout) ----------------
struct FinP { const float* Hin; const uint32_t* Wp; const float* bo; };

__global__ __launch_bounds__(256, 1) void final_mma_kernel(FinP pm, FinP ps,
                                                           const float* __restrict__ gamma,
                                                           const float* __restrict__ beta,
                                                           float* __restrict__ out, int n) {
    extern __shared__ uint32_t smw[];
    FinP P = blockIdx.y ? ps : pm;
    int row0 = blockIdx.x * 128;
    int t = threadIdx.x, lane = t & 31, wid = t >> 5;
    int wm = wid >> 1, wn = wid & 1;
    int ra = wm * 32 + (lane >> 2);
    int kq = lane & 3;
    int nb = wn * 64 + (lane >> 2);

    load_A_bf(P.Hin, row0, n, smw, t);
    copy_W(P.Wp, smw, t);
    __syncthreads();

    float acc[2][8][4];
    zero_acc(acc);
    gemm3(smw, acc, ra, kq, nb);
    __syncthreads();

    // stage C + bo into smem float grid, stride 133 (conflict-free row reads)
    float* gS = (float*)smw;
#pragma unroll
    for (int i = 0; i < 2; i++) {
#pragma unroll
        for (int j = 0; j < 8; j++) {
            int rl = wm * 32 + i * 16 + (lane >> 2);
            int c0 = wn * 64 + j * 8 + 2 * kq;
            float bb0 = __ldg(&P.bo[c0]), bb1 = __ldg(&P.bo[c0 + 1]);
            gS[rl * 133 + c0]       = acc[i][j][0] + bb0;
            gS[rl * 133 + c0 + 1]   = acc[i][j][1] + bb1;
            gS[(rl + 8) * 133 + c0]     = acc[i][j][2] + bb0;
            gS[(rl + 8) * 133 + c0 + 1] = acc[i][j][3] + bb1;
        }
    }
    __syncthreads();

    if (t < 128) {
        int r = row0 + t;
        if (r < n) {
            const float* rowp = gS + t * 133;
            float sum = 0.f;
#pragma unroll 8
            for (int c = 0; c < 128; c++) sum += rowp[c];
            float mean = sum * (1.0f / 128.0f);
            float ss = 0.f;
#pragma unroll 8
            for (int c = 0; c < 128; c++) {
                float d = rowp[c] - mean;
                ss += d * d;
            }
            float inv = rsqrtf(ss * (1.0f / 128.0f) + 1e-5f);
            float* op = out + (size_t)(1 + blockIdx.y) * (size_t)n * DIM + (size_t)r * DIM;
#pragma unroll 4
            for (int c = 0; c < 128; c += 4) {
                float4 o;
                o.x = fmaf((rowp[c]     - mean) * inv, __ldg(&gamma[c]),     __ldg(&beta[c]));
                o.y = fmaf((rowp[c + 1] - mean) * inv, __ldg(&gamma[c + 1]), __ldg(&beta[c + 1]));
                o.z = fmaf((rowp[c + 2] - mean) * inv, __ldg(&gamma[c + 2]), __ldg(&beta[c + 2]));
                o.w = fmaf((rowp[c + 3] - mean) * inv, __ldg(&gamma[c + 3]), __ldg(&beta[c + 3]));
                *(float4*)(op + c) = o;
            }
        }
    }
}

// ---------------- threefry noise + reparameterized sample ----------------
__device__ __forceinline__ uint32_t rotl32(uint32_t x, int r) {
    return (x << r) | (x >> (32 - r));
}
__device__ __forceinline__ float bits_to_normal(uint32_t b) {
    uint32_t fb = (b >> 9) | 0x3F800000u;
    float u = __uint_as_float(fb) - 1.0f;
    const float lo = -0.99999994f;
    float v = fmaf(u, 2.0f, lo);
    v = fmaxf(v, lo);
    float w = -log1pf(-v * v);
    float p;
    if (w < 5.0f) {
        w -= 2.5f;
        p = 2.81022636e-08f;
        p = fmaf(p, w, 3.43273939e-07f);
        p = fmaf(p, w, -3.5233877e-06f);
        p = fmaf(p, w, -4.39150654e-06f);
        p = fmaf(p, w, 0.00021858087f);
        p = fmaf(p, w, -0.00125372503f);
        p = fmaf(p, w, -0.00417768164f);
        p = fmaf(p, w, 0.246640727f);
        p = fmaf(p, w, 1.50140941f);
    } else {
        w = sqrtf(w) - 3.0f;
        p = -0.000200214257f;
        p = fmaf(p, w, 0.000100950558f);
        p = fmaf(p, w, 0.00134934322f);
        p = fmaf(p, w, -0.00367342844f);
        p = fmaf(p, w, 0.00573950773f);
        p = fmaf(p, w, -0.0076224613f);
        p = fmaf(p, w, 0.00943887047f);
        p = fmaf(p, w, 1.00167406f);
        p = fmaf(p, w, 2.83297682f);
    }
    return 1.41421356237f * (p * v);
}

__global__ void sample_kernel(float* __restrict__ out, int total) {
    int f = blockIdx.x * blockDim.x + threadIdx.x;
    if (f >= total) return;
    const uint32_t ks0 = 0u, ks1 = 42u;
    const uint32_t ks2 = ks0 ^ ks1 ^ 0x1BD11BDAu;
    uint32_t x0 = 0u + ks0;
    uint32_t x1 = (uint32_t)f + ks1;
#define TFR(r) { x0 += x1; x1 = rotl32(x1, (r)) ^ x0; }
    TFR(13) TFR(15) TFR(26) TFR(6)   x0 += ks1; x1 += ks2 + 1u;
    TFR(17) TFR(29) TFR(16) TFR(24)  x0 += ks2; x1 += ks0 + 2u;
    TFR(13) TFR(15) TFR(26) TFR(6)   x0 += ks0; x1 += ks1 + 3u;
    TFR(17) TFR(29) TFR(16) TFR(24)  x0 += ks1; x1 += ks2 + 4u;
    TFR(13) TFR(15) TFR(26) TFR(6)   x0 += ks2; x1 += ks0 + 5u;
#undef TFR
    uint32_t bits = x0 ^ x1;
    float eps = bits_to_normal(bits);
    const float* mv = out + total;
    const float* sv = out + 2 * total;
    out[f] = fmaf(eps, sv[f], mv[f]);
}

// ---------------- launch ----------------
extern "C" void kernel_launch(void* const* d_in, const int* in_sizes, int n_in,
                              void* d_out, int out_size) {
    const float* x    = (const float*)d_in[0];
    const int*   esrc = (const int*)d_in[1];
    const int*   edst = (const int*)d_in[2];
    const float* mW1  = (const float*)d_in[3];
    const float* mb1  = (const float*)d_in[4];
    const float* mW2  = (const float*)d_in[5];
    const float* mb2  = (const float*)d_in[6];
    const float* meps = (const float*)d_in[7];
    const float* mWo  = (const float*)d_in[8];
    const float* mbo  = (const float*)d_in[9];
    const float* sW1  = (const float*)d_in[10];
    const float* sb1  = (const float*)d_in[11];
    const float* sW2  = (const float*)d_in[12];
    const float* sb2  = (const float*)d_in[13];
    const float* seps = (const float*)d_in[14];
    const float* sWo  = (const float*)d_in[15];
    const float* sbo  = (const float*)d_in[16];
    const float* lng  = (const float*)d_in[17];
    const float* lnb  = (const float*)d_in[18];

    int n = in_sizes[0] / DIM;
    int e = in_sizes[1];
    int total = n * DIM;
    float* out = (float*)d_out;

    void* p;
    cudaGetSymbolAddress(&p, g_u); float* u0 = (float*)p; float* u1 = u0 + ND;
    cudaGetSymbolAddress(&p, g_h); float* h0 = (float*)p; float* h1 = h0 + ND;
    cudaGetSymbolAddress(&p, g_wprep); uint32_t* wp = (uint32_t*)p;

    cudaFuncSetAttribute(mlp_mma_kernel, cudaFuncAttributeMaxDynamicSharedMemorySize, SMEM_BYTES);
    cudaFuncSetAttribute(final_mma_kernel, cudaFuncAttributeMaxDynamicSharedMemorySize, SMEM_BYTES);
    cudaFuncSetAttribute(prep_kernel, cudaFuncAttributeMaxDynamicSharedMemorySize, 128 * 130 * 4);

    // weight prep (slot = path*7 + layer*2 + mat ; Wout at path*7+6)
    PrepArgs pa;
    for (int pth = 0; pth < 2; pth++) {
        const float* W1 = pth ? sW1 : mW1;
        const float* W2 = pth ? sW2 : mW2;
        const float* Wo = pth ? sWo : mWo;
        for (int l = 0; l < 3; l++) {
            pa.src[pth * 7 + l * 2 + 0] = W1 + l * 16384;
            pa.src[pth * 7 + l * 2 + 1] = W2 + l * 16384;
        }
        pa.src[pth * 7 + 6] = Wo;
    }
    prep_kernel<<<14, 256, 128 * 130 * 4>>>(pa);

    // CSR by destination
    int nblk = (n + SCAN_BLK - 1) / SCAN_BLK;    // 49 <= MAX_PARTS
    zero_deg_kernel<<<(n + 256) / 256, 256>>>(n);
    hist_kernel<<<(e + 255) / 256, 256>>>(edst, e);
    scan_p1<<<nblk, SCAN_BLK>>>(n);
    scan_p2<<<1, 32>>>(nblk);
    scan_p3<<<nblk, SCAN_BLK>>>(n);
    fill_kernel<<<(e + 255) / 256, 256>>>(esrc, edst, e);

    int spmm_blocks = (n * 32 + 255) / 256;
    int gx = (n + 127) / 128;
    dim3 g2(gx, 2);

    for (int l = 0; l < 3; l++) {
        const float* hm_in = (l == 0) ? x : h0;
        const float* hs_in = (l == 0) ? x : h1;
        spmm_kernel<<<spmm_blocks, 256>>>(hm_in, hs_in, meps, seps, l, u0, u1, l == 0, n);
        MlpP pmm{u0, wp + (0 * 7 + 2 * l) * 16384, wp + (0 * 7 + 2 * l + 1) * 16384,
                 mb1 + l * DIM, mb2 + l * DIM, h0};
        MlpP pss{u1, wp + (1 * 7 + 2 * l) * 16384, wp + (1 * 7 + 2 * l + 1) * 16384,
                 sb1 + l * DIM, sb2 + l * DIM, h1};
        mlp_mma_kernel<<<g2, 256, SMEM_BYTES>>>(pmm, pss, n);
    }

    FinP fm{h0, wp + 6 * 16384, mbo};
    FinP fs{h1, wp + 13 * 16384, sbo};
    final_mma_kernel<<<g2, 256, SMEM_BYTES>>>(fm, fs, lng, lnb, out, n);

    sample_kernel<<<(total + 255) / 256, 256>>>(out, total);
}